// round 4
// baseline (speedup 1.0000x reference)
#include <cuda_runtime.h>
#include <cstdint>
#include <math.h>
#include <complex>

// Problem constants
#define S_LEN 128
#define B_SZ  128
#define H_DIM 8
#define T_OUT 12
#define NROWS (S_LEN * B_SZ)
#define N_RAW 30
#define MAX_EMIT 30

#define SCAN_BLOCKS 32
#define HEAD_BLOCKS 116
#define GRID_BLOCKS (SCAN_BLOCKS + HEAD_BLOCKS)   // 148 = one block per SM, wave 1
#define NHEADW (HEAD_BLOCKS * 4)                  // 464 consumer warps

// ---------------------------------------------------------------------------
// Device scratch
// ---------------------------------------------------------------------------
__device__ int   g_is64;
__device__ float g_zx[NROWS * 32];
__device__ float g_h[NROWS * H_DIM];
__device__ int   g_flag[NROWS];

struct QOp { int type; int a; int b; float u[8]; };
struct QOpsParam { int n; QOp ops[MAX_EMIT]; };

// ---------------------------------------------------------------------------
// Fast helpers
// ---------------------------------------------------------------------------
__device__ __forceinline__ float fast_rcp(float x){ float r; asm("rcp.approx.f32 %0,%1;":"=f"(r):"f"(x)); return r; }
__device__ __forceinline__ float fast_ex2(float x){ float r; asm("ex2.approx.f32 %0,%1;":"=f"(r):"f"(x)); return r; }
__device__ __forceinline__ float fast_exp(float x){ return fast_ex2(x * 1.4426950408889634f); }
__device__ __forceinline__ float fast_sigmoid(float x){ return fast_rcp(1.f + fast_exp(-x)); }
__device__ __forceinline__ float fast_tanh(float x){
    x = fminf(fmaxf(x, -9.f), 9.f);
    float e = fast_exp(2.f * x);
    return (e - 1.f) * fast_rcp(e + 1.f);
}
__device__ __forceinline__ int ld_acquire(const int* p){
    int v; asm volatile("ld.acquire.gpu.global.b32 %0,[%1];":"=r"(v):"l"(p):"memory"); return v;
}
__device__ __forceinline__ void st_release(int* p, int v){
    asm volatile("st.release.gpu.global.b32 [%0],%1;"::"l"(p),"r"(v):"memory");
}

// ---------------------------------------------------------------------------
// Kernel 0: detect int32 vs int64. 1024 threads, 4 strided loads each (MLP=4).
// ---------------------------------------------------------------------------
__global__ __launch_bounds__(1024) void detect_kernel(const int* __restrict__ sent) {
    __shared__ int sh[32];
    int tid = threadIdx.x;
    int acc = 0;
    #pragma unroll
    for (int k = 0; k < 4; k++) {
        int i = 2 * (tid + k * 1024) + 1;   // odd words of first 4096 int64 slots
        acc |= sent[i];
    }
    #pragma unroll
    for (int off = 16; off; off >>= 1) acc |= __shfl_xor_sync(~0u, acc, off);
    if ((tid & 31) == 0) sh[tid >> 5] = acc;
    __syncthreads();
    if (tid < 32) {
        int v = sh[tid];
        #pragma unroll
        for (int off = 16; off; off >>= 1) v |= __shfl_xor_sync(~0u, v, off);
        if (tid == 0) g_is64 = (v == 0) ? 1 : 0;
    }
}

// ---------------------------------------------------------------------------
// Kernel 1: zx + flag clearing (stream-ordered before the fused kernel).
// ---------------------------------------------------------------------------
__global__ __launch_bounds__(128) void zx_kernel(
    const float* __restrict__ emb, const float* __restrict__ Win,
    const float* __restrict__ b_in, const float* __restrict__ phi,
    const void* __restrict__ sent)
{
    __shared__ float sW[32 * 65];
    __shared__ float sBP[32];
    int tid = threadIdx.x, lane = tid & 31, wid = tid >> 5;
    int gid = blockIdx.x * 128 + tid;
    if (gid < NROWS) g_flag[gid] = 0;
    for (int i = tid; i < 32 * 64; i += 128) {
        int t = i >> 6, f = i & 63;
        sW[t * 65 + f] = Win[t * 72 + f];
    }
    if (tid < 32) sBP[tid] = b_in[tid] + phi[tid];
    __syncthreads();

    int m = blockIdx.x * 4 + wid;
    long long tok;
    if (g_is64) tok = ((const long long*)sent)[m];
    else        tok = (long long)(((const int*)sent)[m]);
    const float* x = emb + (size_t)tok * 64;
    float x0 = x[lane];
    float x1 = x[32 + lane];

    float acc = sBP[lane];
    const float* wr = &sW[lane * 65];
    #pragma unroll
    for (int f = 0; f < 32; f++) acc = fmaf(__shfl_sync(~0u, x0, f), wr[f], acc);
    #pragma unroll
    for (int f = 0; f < 32; f++) acc = fmaf(__shfl_sync(~0u, x1, f), wr[32 + f], acc);
    g_zx[m * 32 + lane] = acc;
}

// ---------------------------------------------------------------------------
// Quantum head device helpers. 256 amps/warp, idx = lane*8 + r; wire w <-> bit 7-w.
// ---------------------------------------------------------------------------
__device__ __forceinline__ void u2_lane(float (&ar)[8], float (&ai)[8],
                                        int lmask, int lane, const float* u) {
    int myb = (lane & lmask) ? 1 : 0;
    float dr = myb ? u[6] : u[0];
    float di = myb ? u[7] : u[1];
    float orr= myb ? u[4] : u[2];
    float oi = myb ? u[5] : u[3];
    #pragma unroll
    for (int r = 0; r < 8; r++) {
        float pr = __shfl_xor_sync(~0u, ar[r], lmask);
        float pi = __shfl_xor_sync(~0u, ai[r], lmask);
        float nr = dr * ar[r] - di * ai[r] + orr * pr - oi * pi;
        float ni = dr * ai[r] + di * ar[r] + orr * pi + oi * pr;
        ar[r] = nr; ai[r] = ni;
    }
}

template <int TM>
__device__ __forceinline__ void u2_reg(float (&ar)[8], float (&ai)[8], const float* u) {
    #pragma unroll
    for (int r = 0; r < 8; r++) {
        if ((r & TM) == 0) {
            const int r1 = r | TM;
            float a0r = ar[r], a0i = ai[r], a1r = ar[r1], a1i = ai[r1];
            ar[r]  = u[0]*a0r - u[1]*a0i + u[2]*a1r - u[3]*a1i;
            ai[r]  = u[0]*a0i + u[1]*a0r + u[2]*a1i + u[3]*a1r;
            ar[r1] = u[4]*a0r - u[5]*a0i + u[6]*a1r - u[7]*a1i;
            ai[r1] = u[4]*a0i + u[5]*a0r + u[6]*a1i + u[7]*a1r;
        }
    }
}

__device__ __forceinline__ void rz_any(float (&ar)[8], float (&ai)[8],
                                       int p, int lane, float c, float s) {
    #pragma unroll
    for (int r = 0; r < 8; r++) {
        int beta = (p >= 3) ? ((lane >> (p - 3)) & 1) : ((r >> p) & 1);
        float sg = beta ? -s : s;
        float nr = fmaf(c, ar[r],  sg * ai[r]);
        float ni = fmaf(c, ai[r], -sg * ar[r]);
        ar[r] = nr; ai[r] = ni;
    }
}

template <int TM>
__device__ __forceinline__ void rx_reg(float (&ar)[8], float (&ai)[8], float c, float s) {
    #pragma unroll
    for (int r = 0; r < 8; r++) {
        if ((r & TM) == 0) {
            const int r1 = r | TM;
            float a0r = ar[r], a0i = ai[r], a1r = ar[r1], a1i = ai[r1];
            ar[r]  = fmaf(c, a0r,  s * a1i);  ai[r]  = fmaf(c, a0i, -s * a1r);
            ar[r1] = fmaf(c, a1r,  s * a0i);  ai[r1] = fmaf(c, a1i, -s * a0r);
        }
    }
}

__device__ __forceinline__ void rx_lane(float (&ar)[8], float (&ai)[8],
                                        int lmask, float c, float s) {
    #pragma unroll
    for (int r = 0; r < 8; r++) {
        float pr = __shfl_xor_sync(~0u, ar[r], lmask);
        float pi = __shfl_xor_sync(~0u, ai[r], lmask);
        float nr = fmaf(c, ar[r],  s * pi);
        float ni = fmaf(c, ai[r], -s * pr);
        ar[r] = nr; ai[r] = ni;
    }
}

template <int TM>
__device__ __forceinline__ void cnot_rr_t(float (&ar)[8], float (&ai)[8], int cm) {
    #pragma unroll
    for (int r = 0; r < 8; r++) {
        if (((r & cm) != 0) && ((r & TM) == 0)) {
            const int r1 = r | TM;
            float tr = ar[r]; ar[r] = ar[r1]; ar[r1] = tr;
            float ti = ai[r]; ai[r] = ai[r1]; ai[r1] = ti;
        }
    }
}

template <int TM>
__device__ __forceinline__ void cnot_lr_t(float (&ar)[8], float (&ai)[8], int ctrl) {
    if (ctrl) {
        #pragma unroll
        for (int r = 0; r < 8; r++) {
            if ((r & TM) == 0) {
                const int r1 = r | TM;
                float tr = ar[r]; ar[r] = ar[r1]; ar[r1] = tr;
                float ti = ai[r]; ai[r] = ai[r1]; ai[r1] = ti;
            }
        }
    }
}

__device__ __forceinline__ void cnot_rl(float (&ar)[8], float (&ai)[8], int cm, int lt) {
    #pragma unroll
    for (int r = 0; r < 8; r++) {
        if (r & cm) {
            float sr = __shfl_xor_sync(~0u, ar[r], lt);
            float si = __shfl_xor_sync(~0u, ai[r], lt);
            ar[r] = sr; ai[r] = si;
        }
    }
}

__device__ __forceinline__ void cnot_ll(float (&ar)[8], float (&ai)[8],
                                        int cmask, int lt, int lane) {
    int ctrl = (lane & cmask) != 0;
    #pragma unroll
    for (int r = 0; r < 8; r++) {
        float sr = __shfl_xor_sync(~0u, ar[r], lt);
        float si = __shfl_xor_sync(~0u, ai[r], lt);
        if (ctrl) { ar[r] = sr; ai[r] = si; }
    }
}

__device__ __forceinline__ void head_row(
    const float* __restrict__ hsrc, int lane,
    float pc, float ps,
    const float* __restrict__ Whead, const float* __restrict__ b_head,
    float* __restrict__ outrow, const QOpsParam& P)
{
    float myc = 1.f, mys = 0.f;
    if (lane < 8) __sincosf(hsrc[lane] * 0.5f, &mys, &myc);
    float lp = 1.f;
    #pragma unroll
    for (int w = 0; w < 5; w++) {
        float cw = __shfl_sync(~0u, myc, w);
        float sw = __shfl_sync(~0u, mys, w);
        lp *= ((lane >> (4 - w)) & 1) ? sw : cw;
    }
    float c5 = __shfl_sync(~0u, myc, 5), s5 = __shfl_sync(~0u, mys, 5);
    float c6 = __shfl_sync(~0u, myc, 6), s6 = __shfl_sync(~0u, mys, 6);
    float c7 = __shfl_sync(~0u, myc, 7), s7 = __shfl_sync(~0u, mys, 7);

    float ar[8], ai[8];
    #pragma unroll
    for (int r = 0; r < 8; r++) {
        ar[r] = lp * ((r & 4) ? s5 : c5) * ((r & 2) ? s6 : c6) * ((r & 1) ? s7 : c7);
        ai[r] = 0.f;
    }

    for (int o = 0; o < P.n; o++) {
        const QOp& op = P.ops[o];
        if (op.type == 1) {
            int pc_ = 7 - op.a, pt = 7 - op.b;
            if (pt < 3) {
                if (pc_ < 3) {
                    int cm = 1 << pc_;
                    switch (pt) {
                        case 0: cnot_rr_t<1>(ar, ai, cm); break;
                        case 1: cnot_rr_t<2>(ar, ai, cm); break;
                        default: cnot_rr_t<4>(ar, ai, cm); break;
                    }
                } else {
                    int ctrl = (lane >> (pc_ - 3)) & 1;
                    switch (pt) {
                        case 0: cnot_lr_t<1>(ar, ai, ctrl); break;
                        case 1: cnot_lr_t<2>(ar, ai, ctrl); break;
                        default: cnot_lr_t<4>(ar, ai, ctrl); break;
                    }
                }
            } else {
                int lt = 1 << (pt - 3);
                if (pc_ < 3) cnot_rl(ar, ai, 1 << pc_, lt);
                else         cnot_ll(ar, ai, 1 << (pc_ - 3), lt, lane);
            }
        } else if (op.type == 2) {
            rz_any(ar, ai, 7 - op.a, lane, op.u[0], op.u[1]);
        } else {
            int p = 7 - op.a;
            if (p < 3) {
                switch (p) {
                    case 0: u2_reg<1>(ar, ai, op.u); break;
                    case 1: u2_reg<2>(ar, ai, op.u); break;
                    default: u2_reg<4>(ar, ai, op.u); break;
                }
            } else {
                u2_lane(ar, ai, 1 << (p - 3), lane, op.u);
            }
        }
    }

    #pragma unroll
    for (int w = 0; w < 5; w++) {
        float cw = __shfl_sync(~0u, pc, w);
        float sw = __shfl_sync(~0u, ps, w);
        rx_lane(ar, ai, 1 << (4 - w), cw, sw);
    }
    {
        float cw = __shfl_sync(~0u, pc, 5), sw = __shfl_sync(~0u, ps, 5);
        rx_reg<4>(ar, ai, cw, sw);
        cw = __shfl_sync(~0u, pc, 6); sw = __shfl_sync(~0u, ps, 6);
        rx_reg<2>(ar, ai, cw, sw);
        cw = __shfl_sync(~0u, pc, 7); sw = __shfl_sync(~0u, ps, 7);
        rx_reg<1>(ar, ai, cw, sw);
    }

    float p[8], tot = 0.f;
    #pragma unroll
    for (int r = 0; r < 8; r++) {
        p[r] = ar[r] * ar[r] + ai[r] * ai[r];
        tot += p[r];
    }
    float z[8];
    #pragma unroll
    for (int w = 0; w < 5; w++) z[w] = ((lane >> (4 - w)) & 1) ? -tot : tot;
    z[5] = (p[0] + p[1] + p[2] + p[3]) - (p[4] + p[5] + p[6] + p[7]);
    z[6] = (p[0] + p[1] + p[4] + p[5]) - (p[2] + p[3] + p[6] + p[7]);
    z[7] = (p[0] + p[2] + p[4] + p[6]) - (p[1] + p[3] + p[5] + p[7]);
    #pragma unroll
    for (int w = 0; w < 8; w++) {
        #pragma unroll
        for (int off = 16; off; off >>= 1)
            z[w] += __shfl_xor_sync(~0u, z[w], off);
    }

    float logit = -1e30f;
    if (lane < 12) {
        logit = b_head[lane];
        #pragma unroll
        for (int k = 0; k < 8; k++) logit = fmaf(z[k], Whead[lane * 8 + k], logit);
    }
    float mx = logit;
    #pragma unroll
    for (int off = 8; off; off >>= 1) mx = fmaxf(mx, __shfl_xor_sync(~0u, mx, off, 16));
    float e = (lane < 12) ? __expf(logit - mx) : 0.f;
    float se = e;
    #pragma unroll
    for (int off = 8; off; off >>= 1) se += __shfl_xor_sync(~0u, se, off, 16);
    if (lane < 12) outrow[lane] = logit - mx - __logf(se);
}

// ---------------------------------------------------------------------------
// Fused kernel, grid = 148 (one block per SM).
// Blocks [0,32): scan producers (4 chains each, one warp per SMSP, exclusive SM).
// Blocks [32,148): head consumers (464 warps).
// ---------------------------------------------------------------------------
__global__ __launch_bounds__(128) void fused_kernel(
    const float* __restrict__ Win, const float* __restrict__ Wout,
    const float* __restrict__ b_out,
    const float* __restrict__ phiq, const float* __restrict__ Whead,
    const float* __restrict__ b_head, float* __restrict__ out, QOpsParam P)
{
    int wid  = threadIdx.x >> 5;
    int lane = threadIdx.x & 31;

    if (blockIdx.x < SCAN_BLOCKS) {
        int b = blockIdx.x * 4 + wid;
        int t = lane;
        int g = t >> 3, q = t & 7;

        float wh[8], wo[8];
        #pragma unroll
        for (int j = 0; j < 8; j++) wh[j] = Win[t * 72 + 64 + j];
        #pragma unroll
        for (int j = 0; j < 8; j++) wo[j] = Wout[t * 8 + j];
        float bo = b_out[t];

        float h = 0.f, c = 0.f;
        float zn = g_zx[b * 32 + t];

        for (int s = 0; s < S_LEN; s++) {
            float z = zn;
            if (s + 1 < S_LEN) zn = g_zx[((s + 1) * B_SZ + b) * 32 + t];
            #pragma unroll
            for (int j = 0; j < 8; j++)
                z = fmaf(__shfl_sync(~0u, h, j), wh[j], z);
            float p = __cosf(z);
            float cj[8];
            #pragma unroll
            for (int j = 0; j < 8; j++) cj[j] = __shfl_sync(~0u, p, (g << 3) + j);
            float acc = wo[7];
            #pragma unroll
            for (int j = 6; j >= 0; j--) acc = fmaf(cj[j + 1], acc, wo[j]);
            float pre = fmaf(cj[0], acc, bo);

            float act = (g == 2) ? fast_tanh(pre) : fast_sigmoid(pre);
            float af = __shfl_sync(~0u, act, q);
            float ii = __shfl_sync(~0u, act, 8 + q);
            float ag = __shfl_sync(~0u, act, 16 + q);
            float ao = __shfl_sync(~0u, act, 24 + q);
            // unconditional compute (junk on lanes >= 8), predicated store
            c = fmaf(af, c, ii * ag);
            h = ao * fast_tanh(c);
            if (t < 8) g_h[(s * B_SZ + b) * H_DIM + t] = h;
            __syncwarp();
            if (t == 0) st_release(&g_flag[s * B_SZ + b], 1);
        }
    } else {
        int hw = (blockIdx.x - SCAN_BLOCKS) * 4 + wid;
        float pc = 1.f, ps = 0.f;
        if (lane < 8) __sincosf(phiq[lane] * 0.5f, &ps, &pc);

        for (int u = hw; u < NROWS; u += NHEADW) {
            if (lane == 0) {
                while (ld_acquire(&g_flag[u]) == 0) __nanosleep(128);
            }
            __syncwarp();
            const float* hsrc = g_h + (size_t)u * H_DIM;
            int row_out = ((u & 127) << 7) + (u >> 7);
            head_row(hsrc, lane, pc, ps, Whead, b_head, out + (size_t)row_out * T_OUT, P);
        }
    }
}

// ---------------------------------------------------------------------------
// Host: numpy-legacy MT19937 (RandomState(1234)) + gate fusion.
// ---------------------------------------------------------------------------
namespace {
struct MTState { uint32_t mt[624]; int mti; };

static void mt_seed(MTState& s, uint32_t seed) {
    s.mt[0] = seed;
    for (int i = 1; i < 624; i++)
        s.mt[i] = 1812433253u * (s.mt[i - 1] ^ (s.mt[i - 1] >> 30)) + (uint32_t)i;
    s.mti = 624;
}
static uint32_t mt_next(MTState& s) {
    if (s.mti >= 624) {
        for (int i = 0; i < 624; i++) {
            uint32_t y = (s.mt[i] & 0x80000000u) | (s.mt[(i + 1) % 624] & 0x7fffffffu);
            s.mt[i] = s.mt[(i + 397) % 624] ^ (y >> 1) ^ ((y & 1u) ? 0x9908b0dfu : 0u);
        }
        s.mti = 0;
    }
    uint32_t y = s.mt[s.mti++];
    y ^= y >> 11;
    y ^= (y << 7) & 0x9d2c5680u;
    y ^= (y << 15) & 0xefc60000u;
    y ^= y >> 18;
    return y;
}
static uint32_t np_randint(MTState& s, uint32_t n) {
    uint32_t rng = n - 1;
    uint32_t mask = rng;
    mask |= mask >> 1; mask |= mask >> 2; mask |= mask >> 4;
    mask |= mask >> 8; mask |= mask >> 16;
    uint32_t v;
    do { v = mt_next(s) & mask; } while (v > rng);
    return v;
}
static double np_double(MTState& s) {
    uint32_t a = mt_next(s) >> 5;
    uint32_t b = mt_next(s) >> 6;
    return ((double)a * 67108864.0 + (double)b) / 9007199254740992.0;
}

typedef std::complex<double> cd;

struct Pend {
    cd m[2][2];
    int count;
    bool allrz;
    void reset() { m[0][0] = 1.0; m[0][1] = 0.0; m[1][0] = 0.0; m[1][1] = 1.0; count = 0; allrz = true; }
};

static void build_ops(QOpsParam& P) {
    MTState m;
    mt_seed(m, 1234u);

    Pend pend[8];
    for (int w = 0; w < 8; w++) pend[w].reset();
    P.n = 0;

    auto flush = [&](int w) {
        if (!pend[w].count) return;
        QOp op{};
        if (pend[w].allrz) {
            op.type = 2; op.a = w; op.b = 0;
            op.u[0] = (float)pend[w].m[0][0].real();
            op.u[1] = (float)(-pend[w].m[0][0].imag());
        } else {
            op.type = 0; op.a = w; op.b = 0;
            op.u[0] = (float)pend[w].m[0][0].real(); op.u[1] = (float)pend[w].m[0][0].imag();
            op.u[2] = (float)pend[w].m[0][1].real(); op.u[3] = (float)pend[w].m[0][1].imag();
            op.u[4] = (float)pend[w].m[1][0].real(); op.u[5] = (float)pend[w].m[1][0].imag();
            op.u[6] = (float)pend[w].m[1][1].real(); op.u[7] = (float)pend[w].m[1][1].imag();
        }
        P.ops[P.n++] = op;
        pend[w].reset();
    };

    for (int k = 0; k < N_RAW; k++) {
        uint32_t kind = np_randint(m, 4);
        if (kind == 3) {
            int c = (int)np_randint(m, 8);
            int t = (int)np_randint(m, 7);
            if (t >= c) t++;
            flush(c); flush(t);
            QOp op{}; op.type = 1; op.a = c; op.b = t;
            P.ops[P.n++] = op;
        } else {
            int g = (int)(kind % 3);
            int w = (int)np_randint(m, 8);
            double ang = 6.283185307179586 * np_double(m);
            double th = (double)(float)ang;
            double c = cos(th * 0.5), s = sin(th * 0.5);
            cd R[2][2];
            if (g == 0) {
                R[0][0] = c; R[0][1] = cd(0, -s);
                R[1][0] = cd(0, -s); R[1][1] = c;
            } else if (g == 1) {
                R[0][0] = c; R[0][1] = -s;
                R[1][0] = s; R[1][1] = c;
            } else {
                R[0][0] = cd(c, -s); R[0][1] = 0.0;
                R[1][0] = 0.0; R[1][1] = cd(c, s);
            }
            cd n00 = R[0][0] * pend[w].m[0][0] + R[0][1] * pend[w].m[1][0];
            cd n01 = R[0][0] * pend[w].m[0][1] + R[0][1] * pend[w].m[1][1];
            cd n10 = R[1][0] * pend[w].m[0][0] + R[1][1] * pend[w].m[1][0];
            cd n11 = R[1][0] * pend[w].m[0][1] + R[1][1] * pend[w].m[1][1];
            pend[w].m[0][0] = n00; pend[w].m[0][1] = n01;
            pend[w].m[1][0] = n10; pend[w].m[1][1] = n11;
            pend[w].count++;
            if (g != 2) pend[w].allrz = false;
        }
    }
    for (int w = 0; w < 8; w++) flush(w);
}
} // namespace

// ---------------------------------------------------------------------------
extern "C" void kernel_launch(void* const* d_in, const int* in_sizes, int n_in,
                              void* d_out, int out_size) {
    (void)in_sizes; (void)n_in; (void)out_size;
    const float* emb    = (const float*)d_in[0];
    const float* Win    = (const float*)d_in[1];
    const float* b_in   = (const float*)d_in[2];
    const float* phi    = (const float*)d_in[3];
    const float* Wout   = (const float*)d_in[4];
    const float* b_out  = (const float*)d_in[5];
    const float* phiq   = (const float*)d_in[6];
    const float* Whead  = (const float*)d_in[7];
    const float* b_head = (const float*)d_in[8];
    const void*  sent   = d_in[9];

    QOpsParam P;
    build_ops(P);

    detect_kernel<<<1, 1024>>>((const int*)sent);
    zx_kernel<<<NROWS / 4, 128>>>(emb, Win, b_in, phi, sent);
    fused_kernel<<<GRID_BLOCKS, 128>>>(Win, Wout, b_out, phiq, Whead, b_head,
                                       (float*)d_out, P);
}

// round 5
// speedup vs baseline: 1.1464x; 1.1464x over previous
#include <cuda_runtime.h>
#include <cstdint>
#include <math.h>
#include <complex>

// Problem constants
#define S_LEN 128
#define B_SZ  128
#define H_DIM 8
#define T_OUT 12
#define NROWS (S_LEN * B_SZ)
#define N_RAW 30
#define MAX_EMIT 30

#define SCAN_SLOTS 32
#define SM_COUNT 148
#define BLOCKS_PER_SM 8
#define GRID_BLOCKS (SM_COUNT * BLOCKS_PER_SM)   // 1184, all co-resident (wave 1)

// ---------------------------------------------------------------------------
// Device scratch
// ---------------------------------------------------------------------------
__device__ float g_zx[NROWS * 32];
__device__ float g_h[NROWS * H_DIM];
__device__ int   g_flag[NROWS];
__device__ int   g_ticket;

struct QOp { int type; int a; int b; float u[8]; };
struct QOpsParam { int n; QOp ops[MAX_EMIT]; };

// ---------------------------------------------------------------------------
// Fast helpers
// ---------------------------------------------------------------------------
__device__ __forceinline__ float fast_rcp(float x){ float r; asm("rcp.approx.f32 %0,%1;":"=f"(r):"f"(x)); return r; }
__device__ __forceinline__ float fast_ex2(float x){ float r; asm("ex2.approx.f32 %0,%1;":"=f"(r):"f"(x)); return r; }
__device__ __forceinline__ float fast_exp(float x){ return fast_ex2(x * 1.4426950408889634f); }
__device__ __forceinline__ float fast_sigmoid(float x){ return fast_rcp(1.f + fast_exp(-x)); }
__device__ __forceinline__ float fast_tanh(float x){
    x = fminf(fmaxf(x, -9.f), 9.f);
    float e = fast_exp(2.f * x);
    return (e - 1.f) * fast_rcp(e + 1.f);
}
__device__ __forceinline__ int ld_acquire(const int* p){
    int v; asm volatile("ld.acquire.gpu.global.b32 %0,[%1];":"=r"(v):"l"(p):"memory"); return v;
}
__device__ __forceinline__ void st_release(int* p, int v){
    asm volatile("st.release.gpu.global.b32 [%0],%1;"::"l"(p),"r"(v):"memory");
}

// ---------------------------------------------------------------------------
// Kernel 1: zx + flag/ticket clearing + inline int64 detection.
// ---------------------------------------------------------------------------
__global__ __launch_bounds__(128) void zx_kernel(
    const float* __restrict__ emb, const float* __restrict__ Win,
    const float* __restrict__ b_in, const float* __restrict__ phi,
    const int* __restrict__ sent32)
{
    __shared__ float sW[32 * 65];
    __shared__ float sBP[32];
    __shared__ int   sIs64;
    int tid = threadIdx.x, lane = tid & 31, wid = tid >> 5;
    int gid = blockIdx.x * 128 + tid;
    if (gid < NROWS) g_flag[gid] = 0;
    if (gid == 0) g_ticket = 0;

    // warp 0: detect int64 by OR of odd 32-bit words over a 64-token window.
    if (wid == 0) {
        int acc = sent32[2 * lane + 1] | sent32[2 * (lane + 32) + 1];
        #pragma unroll
        for (int off = 16; off; off >>= 1) acc |= __shfl_xor_sync(~0u, acc, off);
        if (lane == 0) sIs64 = (acc == 0) ? 1 : 0;
    }
    for (int i = tid; i < 32 * 64; i += 128) {
        int t = i >> 6, f = i & 63;
        sW[t * 65 + f] = Win[t * 72 + f];
    }
    if (tid < 32) sBP[tid] = b_in[tid] + phi[tid];
    __syncthreads();

    int m = blockIdx.x * 4 + wid;
    int tok = sIs64 ? sent32[2 * m] : sent32[m];
    const float* x = emb + (size_t)tok * 64;
    float x0 = x[lane];
    float x1 = x[32 + lane];

    float acc = sBP[lane];
    const float* wr = &sW[lane * 65];
    #pragma unroll
    for (int f = 0; f < 32; f++) acc = fmaf(__shfl_sync(~0u, x0, f), wr[f], acc);
    #pragma unroll
    for (int f = 0; f < 32; f++) acc = fmaf(__shfl_sync(~0u, x1, f), wr[32 + f], acc);
    g_zx[m * 32 + lane] = acc;
}

// ---------------------------------------------------------------------------
// Quantum head device helpers. 256 amps/warp, idx = lane*8 + r; wire w <-> bit 7-w.
// ---------------------------------------------------------------------------
__device__ __forceinline__ void u2_lane(float (&ar)[8], float (&ai)[8],
                                        int lmask, int lane, const float* u) {
    int myb = (lane & lmask) ? 1 : 0;
    float dr = myb ? u[6] : u[0];
    float di = myb ? u[7] : u[1];
    float orr= myb ? u[4] : u[2];
    float oi = myb ? u[5] : u[3];
    #pragma unroll
    for (int r = 0; r < 8; r++) {
        float pr = __shfl_xor_sync(~0u, ar[r], lmask);
        float pi = __shfl_xor_sync(~0u, ai[r], lmask);
        float nr = dr * ar[r] - di * ai[r] + orr * pr - oi * pi;
        float ni = dr * ai[r] + di * ar[r] + orr * pi + oi * pr;
        ar[r] = nr; ai[r] = ni;
    }
}

template <int TM>
__device__ __forceinline__ void u2_reg(float (&ar)[8], float (&ai)[8], const float* u) {
    #pragma unroll
    for (int r = 0; r < 8; r++) {
        if ((r & TM) == 0) {
            const int r1 = r | TM;
            float a0r = ar[r], a0i = ai[r], a1r = ar[r1], a1i = ai[r1];
            ar[r]  = u[0]*a0r - u[1]*a0i + u[2]*a1r - u[3]*a1i;
            ai[r]  = u[0]*a0i + u[1]*a0r + u[2]*a1i + u[3]*a1r;
            ar[r1] = u[4]*a0r - u[5]*a0i + u[6]*a1r - u[7]*a1i;
            ai[r1] = u[4]*a0i + u[5]*a0r + u[6]*a1i + u[7]*a1r;
        }
    }
}

__device__ __forceinline__ void rz_any(float (&ar)[8], float (&ai)[8],
                                       int p, int lane, float c, float s) {
    #pragma unroll
    for (int r = 0; r < 8; r++) {
        int beta = (p >= 3) ? ((lane >> (p - 3)) & 1) : ((r >> p) & 1);
        float sg = beta ? -s : s;
        float nr = fmaf(c, ar[r],  sg * ai[r]);
        float ni = fmaf(c, ai[r], -sg * ar[r]);
        ar[r] = nr; ai[r] = ni;
    }
}

template <int TM>
__device__ __forceinline__ void rx_reg(float (&ar)[8], float (&ai)[8], float c, float s) {
    #pragma unroll
    for (int r = 0; r < 8; r++) {
        if ((r & TM) == 0) {
            const int r1 = r | TM;
            float a0r = ar[r], a0i = ai[r], a1r = ar[r1], a1i = ai[r1];
            ar[r]  = fmaf(c, a0r,  s * a1i);  ai[r]  = fmaf(c, a0i, -s * a1r);
            ar[r1] = fmaf(c, a1r,  s * a0i);  ai[r1] = fmaf(c, a1i, -s * a0r);
        }
    }
}

__device__ __forceinline__ void rx_lane(float (&ar)[8], float (&ai)[8],
                                        int lmask, float c, float s) {
    #pragma unroll
    for (int r = 0; r < 8; r++) {
        float pr = __shfl_xor_sync(~0u, ar[r], lmask);
        float pi = __shfl_xor_sync(~0u, ai[r], lmask);
        float nr = fmaf(c, ar[r],  s * pi);
        float ni = fmaf(c, ai[r], -s * pr);
        ar[r] = nr; ai[r] = ni;
    }
}

template <int TM>
__device__ __forceinline__ void cnot_rr_t(float (&ar)[8], float (&ai)[8], int cm) {
    #pragma unroll
    for (int r = 0; r < 8; r++) {
        if (((r & cm) != 0) && ((r & TM) == 0)) {
            const int r1 = r | TM;
            float tr = ar[r]; ar[r] = ar[r1]; ar[r1] = tr;
            float ti = ai[r]; ai[r] = ai[r1]; ai[r1] = ti;
        }
    }
}

template <int TM>
__device__ __forceinline__ void cnot_lr_t(float (&ar)[8], float (&ai)[8], int ctrl) {
    if (ctrl) {
        #pragma unroll
        for (int r = 0; r < 8; r++) {
            if ((r & TM) == 0) {
                const int r1 = r | TM;
                float tr = ar[r]; ar[r] = ar[r1]; ar[r1] = tr;
                float ti = ai[r]; ai[r] = ai[r1]; ai[r1] = ti;
            }
        }
    }
}

__device__ __forceinline__ void cnot_rl(float (&ar)[8], float (&ai)[8], int cm, int lt) {
    #pragma unroll
    for (int r = 0; r < 8; r++) {
        if (r & cm) {
            float sr = __shfl_xor_sync(~0u, ar[r], lt);
            float si = __shfl_xor_sync(~0u, ai[r], lt);
            ar[r] = sr; ai[r] = si;
        }
    }
}

__device__ __forceinline__ void cnot_ll(float (&ar)[8], float (&ai)[8],
                                        int cmask, int lt, int lane) {
    int ctrl = (lane & cmask) != 0;
    #pragma unroll
    for (int r = 0; r < 8; r++) {
        float sr = __shfl_xor_sync(~0u, ar[r], lt);
        float si = __shfl_xor_sync(~0u, ai[r], lt);
        if (ctrl) { ar[r] = sr; ai[r] = si; }
    }
}

__device__ __forceinline__ void head_row(
    const float* __restrict__ hsrc, int lane,
    float pc, float ps,
    const float* __restrict__ Whead, const float* __restrict__ b_head,
    float* __restrict__ outrow, const QOpsParam& P)
{
    float myc = 1.f, mys = 0.f;
    if (lane < 8) __sincosf(hsrc[lane] * 0.5f, &mys, &myc);
    float lp = 1.f;
    #pragma unroll
    for (int w = 0; w < 5; w++) {
        float cw = __shfl_sync(~0u, myc, w);
        float sw = __shfl_sync(~0u, mys, w);
        lp *= ((lane >> (4 - w)) & 1) ? sw : cw;
    }
    float c5 = __shfl_sync(~0u, myc, 5), s5 = __shfl_sync(~0u, mys, 5);
    float c6 = __shfl_sync(~0u, myc, 6), s6 = __shfl_sync(~0u, mys, 6);
    float c7 = __shfl_sync(~0u, myc, 7), s7 = __shfl_sync(~0u, mys, 7);

    float ar[8], ai[8];
    #pragma unroll
    for (int r = 0; r < 8; r++) {
        ar[r] = lp * ((r & 4) ? s5 : c5) * ((r & 2) ? s6 : c6) * ((r & 1) ? s7 : c7);
        ai[r] = 0.f;
    }

    for (int o = 0; o < P.n; o++) {
        const QOp& op = P.ops[o];
        if (op.type == 1) {
            int pc_ = 7 - op.a, pt = 7 - op.b;
            if (pt < 3) {
                if (pc_ < 3) {
                    int cm = 1 << pc_;
                    switch (pt) {
                        case 0: cnot_rr_t<1>(ar, ai, cm); break;
                        case 1: cnot_rr_t<2>(ar, ai, cm); break;
                        default: cnot_rr_t<4>(ar, ai, cm); break;
                    }
                } else {
                    int ctrl = (lane >> (pc_ - 3)) & 1;
                    switch (pt) {
                        case 0: cnot_lr_t<1>(ar, ai, ctrl); break;
                        case 1: cnot_lr_t<2>(ar, ai, ctrl); break;
                        default: cnot_lr_t<4>(ar, ai, ctrl); break;
                    }
                }
            } else {
                int lt = 1 << (pt - 3);
                if (pc_ < 3) cnot_rl(ar, ai, 1 << pc_, lt);
                else         cnot_ll(ar, ai, 1 << (pc_ - 3), lt, lane);
            }
        } else if (op.type == 2) {
            rz_any(ar, ai, 7 - op.a, lane, op.u[0], op.u[1]);
        } else {
            int p = 7 - op.a;
            if (p < 3) {
                switch (p) {
                    case 0: u2_reg<1>(ar, ai, op.u); break;
                    case 1: u2_reg<2>(ar, ai, op.u); break;
                    default: u2_reg<4>(ar, ai, op.u); break;
                }
            } else {
                u2_lane(ar, ai, 1 << (p - 3), lane, op.u);
            }
        }
    }

    #pragma unroll
    for (int w = 0; w < 5; w++) {
        float cw = __shfl_sync(~0u, pc, w);
        float sw = __shfl_sync(~0u, ps, w);
        rx_lane(ar, ai, 1 << (4 - w), cw, sw);
    }
    {
        float cw = __shfl_sync(~0u, pc, 5), sw = __shfl_sync(~0u, ps, 5);
        rx_reg<4>(ar, ai, cw, sw);
        cw = __shfl_sync(~0u, pc, 6); sw = __shfl_sync(~0u, ps, 6);
        rx_reg<2>(ar, ai, cw, sw);
        cw = __shfl_sync(~0u, pc, 7); sw = __shfl_sync(~0u, ps, 7);
        rx_reg<1>(ar, ai, cw, sw);
    }

    float p[8], tot = 0.f;
    #pragma unroll
    for (int r = 0; r < 8; r++) {
        p[r] = ar[r] * ar[r] + ai[r] * ai[r];
        tot += p[r];
    }
    float z[8];
    #pragma unroll
    for (int w = 0; w < 5; w++) z[w] = ((lane >> (4 - w)) & 1) ? -tot : tot;
    z[5] = (p[0] + p[1] + p[2] + p[3]) - (p[4] + p[5] + p[6] + p[7]);
    z[6] = (p[0] + p[1] + p[4] + p[5]) - (p[2] + p[3] + p[6] + p[7]);
    z[7] = (p[0] + p[2] + p[4] + p[6]) - (p[1] + p[3] + p[5] + p[7]);
    #pragma unroll
    for (int w = 0; w < 8; w++) {
        #pragma unroll
        for (int off = 16; off; off >>= 1)
            z[w] += __shfl_xor_sync(~0u, z[w], off);
    }

    float logit = -1e30f;
    if (lane < 12) {
        logit = b_head[lane];
        #pragma unroll
        for (int k = 0; k < 8; k++) logit = fmaf(z[k], Whead[lane * 8 + k], logit);
    }
    float mx = logit;
    #pragma unroll
    for (int off = 8; off; off >>= 1) mx = fmaxf(mx, __shfl_xor_sync(~0u, mx, off, 16));
    float e = (lane < 12) ? __expf(logit - mx) : 0.f;
    float se = e;
    #pragma unroll
    for (int off = 8; off; off >>= 1) se += __shfl_xor_sync(~0u, se, off, 16);
    if (lane < 12) outrow[lane] = logit - mx - __logf(se);
}

// Consumer loop: pull rows from the global ticket queue until drained.
__device__ __forceinline__ void consume_rows(
    int lane,
    const float* __restrict__ phiq, const float* __restrict__ Whead,
    const float* __restrict__ b_head, float* __restrict__ out,
    const QOpsParam& P)
{
    float pc = 1.f, ps = 0.f;
    if (lane < 8) __sincosf(phiq[lane] * 0.5f, &ps, &pc);

    for (;;) {
        int u = 0;
        if (lane == 0) u = atomicAdd(&g_ticket, 1);
        u = __shfl_sync(~0u, u, 0);
        if (u >= NROWS) break;
        if (lane == 0) {
            while (ld_acquire(&g_flag[u]) == 0) __nanosleep(64);
        }
        __syncwarp();
        const float* hsrc = g_h + (size_t)u * H_DIM;
        int row_out = ((u & 127) << 7) + (u >> 7);   // (s_out*128 + b_out)
        head_row(hsrc, lane, pc, ps, Whead, b_head, out + (size_t)row_out * T_OUT, P);
    }
}

// ---------------------------------------------------------------------------
// Fused kernel, grid = 1184 (8 blocks per SM, all co-resident in wave 1).
// slot = bid % 148. slot < 32: scan (bid < 148 only; duplicates exit -> scan
// warps keep their SMSPs exclusive). slot >= 32: consumers (8 blocks/SM).
// Scan blocks join the consumer queue after producing all rows.
// ---------------------------------------------------------------------------
__global__ __launch_bounds__(128, 8) void fused_kernel(
    const float* __restrict__ Win, const float* __restrict__ Wout,
    const float* __restrict__ b_out,
    const float* __restrict__ phiq, const float* __restrict__ Whead,
    const float* __restrict__ b_head, float* __restrict__ out, QOpsParam P)
{
    int wid  = threadIdx.x >> 5;
    int lane = threadIdx.x & 31;
    int slot = blockIdx.x % SM_COUNT;

    if (slot < SCAN_SLOTS) {
        if (blockIdx.x >= SM_COUNT) return;   // free the scan SM's other slots

        int b = slot * 4 + wid;
        int t = lane;
        int g = t >> 3, q = t & 7;

        float wh[8], wo[8];
        #pragma unroll
        for (int j = 0; j < 8; j++) wh[j] = Win[t * 72 + 64 + j];
        #pragma unroll
        for (int j = 0; j < 8; j++) wo[j] = Wout[t * 8 + j];
        float bo = b_out[t];

        float h = 0.f, c = 0.f;
        float zn = g_zx[b * 32 + t];

        for (int s = 0; s < S_LEN; s++) {
            float z = zn;
            if (s + 1 < S_LEN) zn = g_zx[((s + 1) * B_SZ + b) * 32 + t];
            #pragma unroll
            for (int j = 0; j < 8; j++)
                z = fmaf(__shfl_sync(~0u, h, j), wh[j], z);
            float p = __cosf(z);
            float cj[8];
            #pragma unroll
            for (int j = 0; j < 8; j++) cj[j] = __shfl_sync(~0u, p, (g << 3) + j);
            float acc = wo[7];
            #pragma unroll
            for (int j = 6; j >= 0; j--) acc = fmaf(cj[j + 1], acc, wo[j]);
            float pre = fmaf(cj[0], acc, bo);

            float act = (g == 2) ? fast_tanh(pre) : fast_sigmoid(pre);
            float af = __shfl_sync(~0u, act, q);
            float ii = __shfl_sync(~0u, act, 8 + q);
            float ag = __shfl_sync(~0u, act, 16 + q);
            float ao = __shfl_sync(~0u, act, 24 + q);
            c = fmaf(af, c, ii * ag);
            h = ao * fast_tanh(c);
            if (t < 8) g_h[(s * B_SZ + b) * H_DIM + t] = h;
            __syncwarp();
            if (t == 0) st_release(&g_flag[s * B_SZ + b], 1);
        }
        // done producing: help drain the head queue
        consume_rows(lane, phiq, Whead, b_head, out, P);
    } else {
        consume_rows(lane, phiq, Whead, b_head, out, P);
    }
}

// ---------------------------------------------------------------------------
// Host: numpy-legacy MT19937 (RandomState(1234)) + gate fusion.
// ---------------------------------------------------------------------------
namespace {
struct MTState { uint32_t mt[624]; int mti; };

static void mt_seed(MTState& s, uint32_t seed) {
    s.mt[0] = seed;
    for (int i = 1; i < 624; i++)
        s.mt[i] = 1812433253u * (s.mt[i - 1] ^ (s.mt[i - 1] >> 30)) + (uint32_t)i;
    s.mti = 624;
}
static uint32_t mt_next(MTState& s) {
    if (s.mti >= 624) {
        for (int i = 0; i < 624; i++) {
            uint32_t y = (s.mt[i] & 0x80000000u) | (s.mt[(i + 1) % 624] & 0x7fffffffu);
            s.mt[i] = s.mt[(i + 397) % 624] ^ (y >> 1) ^ ((y & 1u) ? 0x9908b0dfu : 0u);
        }
        s.mti = 0;
    }
    uint32_t y = s.mt[s.mti++];
    y ^= y >> 11;
    y ^= (y << 7) & 0x9d2c5680u;
    y ^= (y << 15) & 0xefc60000u;
    y ^= y >> 18;
    return y;
}
static uint32_t np_randint(MTState& s, uint32_t n) {
    uint32_t rng = n - 1;
    uint32_t mask = rng;
    mask |= mask >> 1; mask |= mask >> 2; mask |= mask >> 4;
    mask |= mask >> 8; mask |= mask >> 16;
    uint32_t v;
    do { v = mt_next(s) & mask; } while (v > rng);
    return v;
}
static double np_double(MTState& s) {
    uint32_t a = mt_next(s) >> 5;
    uint32_t b = mt_next(s) >> 6;
    return ((double)a * 67108864.0 + (double)b) / 9007199254740992.0;
}

typedef std::complex<double> cd;

struct Pend {
    cd m[2][2];
    int count;
    bool allrz;
    void reset() { m[0][0] = 1.0; m[0][1] = 0.0; m[1][0] = 0.0; m[1][1] = 1.0; count = 0; allrz = true; }
};

static void build_ops(QOpsParam& P) {
    MTState m;
    mt_seed(m, 1234u);

    Pend pend[8];
    for (int w = 0; w < 8; w++) pend[w].reset();
    P.n = 0;

    auto flush = [&](int w) {
        if (!pend[w].count) return;
        QOp op{};
        if (pend[w].allrz) {
            op.type = 2; op.a = w; op.b = 0;
            op.u[0] = (float)pend[w].m[0][0].real();
            op.u[1] = (float)(-pend[w].m[0][0].imag());
        } else {
            op.type = 0; op.a = w; op.b = 0;
            op.u[0] = (float)pend[w].m[0][0].real(); op.u[1] = (float)pend[w].m[0][0].imag();
            op.u[2] = (float)pend[w].m[0][1].real(); op.u[3] = (float)pend[w].m[0][1].imag();
            op.u[4] = (float)pend[w].m[1][0].real(); op.u[5] = (float)pend[w].m[1][0].imag();
            op.u[6] = (float)pend[w].m[1][1].real(); op.u[7] = (float)pend[w].m[1][1].imag();
        }
        P.ops[P.n++] = op;
        pend[w].reset();
    };

    for (int k = 0; k < N_RAW; k++) {
        uint32_t kind = np_randint(m, 4);
        if (kind == 3) {
            int c = (int)np_randint(m, 8);
            int t = (int)np_randint(m, 7);
            if (t >= c) t++;
            flush(c); flush(t);
            QOp op{}; op.type = 1; op.a = c; op.b = t;
            P.ops[P.n++] = op;
        } else {
            int g = (int)(kind % 3);
            int w = (int)np_randint(m, 8);
            double ang = 6.283185307179586 * np_double(m);
            double th = (double)(float)ang;
            double c = cos(th * 0.5), s = sin(th * 0.5);
            cd R[2][2];
            if (g == 0) {
                R[0][0] = c; R[0][1] = cd(0, -s);
                R[1][0] = cd(0, -s); R[1][1] = c;
            } else if (g == 1) {
                R[0][0] = c; R[0][1] = -s;
                R[1][0] = s; R[1][1] = c;
            } else {
                R[0][0] = cd(c, -s); R[0][1] = 0.0;
                R[1][0] = 0.0; R[1][1] = cd(c, s);
            }
            cd n00 = R[0][0] * pend[w].m[0][0] + R[0][1] * pend[w].m[1][0];
            cd n01 = R[0][0] * pend[w].m[0][1] + R[0][1] * pend[w].m[1][1];
            cd n10 = R[1][0] * pend[w].m[0][0] + R[1][1] * pend[w].m[1][0];
            cd n11 = R[1][0] * pend[w].m[0][1] + R[1][1] * pend[w].m[1][1];
            pend[w].m[0][0] = n00; pend[w].m[0][1] = n01;
            pend[w].m[1][0] = n10; pend[w].m[1][1] = n11;
            pend[w].count++;
            if (g != 2) pend[w].allrz = false;
        }
    }
    for (int w = 0; w < 8; w++) flush(w);
}
} // namespace

// ---------------------------------------------------------------------------
extern "C" void kernel_launch(void* const* d_in, const int* in_sizes, int n_in,
                              void* d_out, int out_size) {
    (void)in_sizes; (void)n_in; (void)out_size;
    const float* emb    = (const float*)d_in[0];
    const float* Win    = (const float*)d_in[1];
    const float* b_in   = (const float*)d_in[2];
    const float* phi    = (const float*)d_in[3];
    const float* Wout   = (const float*)d_in[4];
    const float* b_out  = (const float*)d_in[5];
    const float* phiq   = (const float*)d_in[6];
    const float* Whead  = (const float*)d_in[7];
    const float* b_head = (const float*)d_in[8];
    const int*   sent   = (const int*)d_in[9];

    QOpsParam P;
    build_ops(P);

    zx_kernel<<<NROWS / 4, 128>>>(emb, Win, b_in, phi, sent);
    fused_kernel<<<GRID_BLOCKS, 128>>>(Win, Wout, b_out, phiq, Whead, b_head,
                                       (float*)d_out, P);
}

// round 7
// speedup vs baseline: 2.2470x; 1.9601x over previous
#include <cuda_runtime.h>
#include <cstdint>
#include <math.h>
#include <complex>

// Problem constants
#define S_LEN 128
#define B_SZ  128
#define H_DIM 8
#define T_OUT 12
#define NROWS (S_LEN * B_SZ)
#define N_RAW 30
#define MAX_EMIT 40

// ---------------------------------------------------------------------------
// Device scratch
// ---------------------------------------------------------------------------
__device__ float g_zx[NROWS * 32];
__device__ float g_h[NROWS * H_DIM];

struct QU { float u[MAX_EMIT * 8]; };   // fused-op coefficients, host-computed

// ---------------------------------------------------------------------------
// Compile-time MT19937 + random-layer structure (types/wires only; no floats).
// Mirrors the host fusion logic EXACTLY (same emission order).
// ---------------------------------------------------------------------------
struct EmitList { int n; int type[MAX_EMIT]; int a[MAX_EMIT]; int b[MAX_EMIT]; };

constexpr uint32_t cmt_next(uint32_t (&mt)[624], int& mti) {
    if (mti >= 624) {
        for (int i = 0; i < 624; i++) {
            uint32_t y = (mt[i] & 0x80000000u) | (mt[(i + 1) % 624] & 0x7fffffffu);
            mt[i] = mt[(i + 397) % 624] ^ (y >> 1) ^ ((y & 1u) ? 0x9908b0dfu : 0u);
        }
        mti = 0;
    }
    uint32_t y = mt[mti++];
    y ^= y >> 11;
    y ^= (y << 7) & 0x9d2c5680u;
    y ^= (y << 15) & 0xefc60000u;
    y ^= y >> 18;
    return y;
}
constexpr uint32_t c_randint(uint32_t (&mt)[624], int& mti, uint32_t n) {
    uint32_t rng = n - 1;
    uint32_t mask = rng;
    mask |= mask >> 1; mask |= mask >> 2; mask |= mask >> 4;
    mask |= mask >> 8; mask |= mask >> 16;
    uint32_t v = cmt_next(mt, mti) & mask;
    while (v > rng) v = cmt_next(mt, mti) & mask;
    return v;
}

constexpr EmitList compute_emitted() {
    uint32_t mt[624] = {};
    mt[0] = 1234u;
    for (int i = 1; i < 624; i++)
        mt[i] = 1812433253u * (mt[i - 1] ^ (mt[i - 1] >> 30)) + (uint32_t)i;
    int mti = 624;

    EmitList E{};
    int cnt[8] = {};
    bool allrz[8] = {true, true, true, true, true, true, true, true};

    for (int k = 0; k < N_RAW; k++) {
        uint32_t kind = c_randint(mt, mti, 4);
        if (kind == 3) {
            int c = (int)c_randint(mt, mti, 8);
            int t = (int)c_randint(mt, mti, 7);
            if (t >= c) t++;
            if (cnt[c]) { E.type[E.n] = allrz[c] ? 2 : 0; E.a[E.n] = c; E.b[E.n] = 0; E.n++; cnt[c] = 0; allrz[c] = true; }
            if (cnt[t]) { E.type[E.n] = allrz[t] ? 2 : 0; E.a[E.n] = t; E.b[E.n] = 0; E.n++; cnt[t] = 0; allrz[t] = true; }
            E.type[E.n] = 1; E.a[E.n] = c; E.b[E.n] = t; E.n++;
        } else {
            int g = (int)(kind % 3);
            int w = (int)c_randint(mt, mti, 8);
            cmt_next(mt, mti); cmt_next(mt, mti);   // the two draws of uniform()
            cnt[w]++;
            if (g != 2) allrz[w] = false;
        }
    }
    for (int w = 0; w < 8; w++)
        if (cnt[w]) { E.type[E.n] = allrz[w] ? 2 : 0; E.a[E.n] = w; E.b[E.n] = 0; E.n++; }
    return E;
}

constexpr EmitList EM = compute_emitted();

// ---------------------------------------------------------------------------
// Fast helpers
// ---------------------------------------------------------------------------
__device__ __forceinline__ float fast_rcp(float x){ float r; asm("rcp.approx.f32 %0,%1;":"=f"(r):"f"(x)); return r; }
__device__ __forceinline__ float fast_ex2(float x){ float r; asm("ex2.approx.f32 %0,%1;":"=f"(r):"f"(x)); return r; }
__device__ __forceinline__ float fast_exp(float x){ return fast_ex2(x * 1.4426950408889634f); }
__device__ __forceinline__ float fast_sigmoid(float x){ return fast_rcp(1.f + fast_exp(-x)); }
__device__ __forceinline__ float fast_tanh(float x){
    x = fminf(fmaxf(x, -9.f), 9.f);
    float e = fast_exp(2.f * x);
    return (e - 1.f) * fast_rcp(e + 1.f);
}

// ---------------------------------------------------------------------------
// Kernel 1: zx[s][b][t] = emb[tok]·Win[t][0:64] + b_in[t] + phi[t]
// Inline int64-vs-int32 sentence detection in warp 0.
// ---------------------------------------------------------------------------
__global__ __launch_bounds__(128) void zx_kernel(
    const float* __restrict__ emb, const float* __restrict__ Win,
    const float* __restrict__ b_in, const float* __restrict__ phi,
    const int* __restrict__ sent32)
{
    __shared__ float sW[32 * 65];
    __shared__ float sBP[32];
    __shared__ int   sIs64;
    int tid = threadIdx.x, lane = tid & 31, wid = tid >> 5;

    if (wid == 0) {
        int acc = sent32[2 * lane + 1] | sent32[2 * (lane + 32) + 1];
        #pragma unroll
        for (int off = 16; off; off >>= 1) acc |= __shfl_xor_sync(~0u, acc, off);
        if (lane == 0) sIs64 = (acc == 0) ? 1 : 0;
    }
    for (int i = tid; i < 32 * 64; i += 128) {
        int t = i >> 6, f = i & 63;
        sW[t * 65 + f] = Win[t * 72 + f];
    }
    if (tid < 32) sBP[tid] = b_in[tid] + phi[tid];
    __syncthreads();

    int m = blockIdx.x * 4 + wid;
    int tok = sIs64 ? sent32[2 * m] : sent32[m];
    const float* x = emb + (size_t)tok * 64;
    float x0 = x[lane];
    float x1 = x[32 + lane];

    float acc = sBP[lane];
    const float* wr = &sW[lane * 65];
    #pragma unroll
    for (int f = 0; f < 32; f++) acc = fmaf(__shfl_sync(~0u, x0, f), wr[f], acc);
    #pragma unroll
    for (int f = 0; f < 32; f++) acc = fmaf(__shfl_sync(~0u, x1, f), wr[32 + f], acc);
    g_zx[m * 32 + lane] = acc;
}

// ---------------------------------------------------------------------------
// Kernel 2: sequential LSTM scan. One warp per chain, one block (warp) per SM.
// ---------------------------------------------------------------------------
__global__ __launch_bounds__(32) void scan_kernel(
    const float* __restrict__ Win, const float* __restrict__ Wout,
    const float* __restrict__ b_out)
{
    int b = blockIdx.x;
    int t = threadIdx.x;
    int g = t >> 3, q = t & 7;

    float wh[8], wo[8];
    #pragma unroll
    for (int j = 0; j < 8; j++) wh[j] = Win[t * 72 + 64 + j];
    #pragma unroll
    for (int j = 0; j < 8; j++) wo[j] = Wout[t * 8 + j];
    float bo = b_out[t];

    float h = 0.f, c = 0.f;
    float zn = g_zx[b * 32 + t];

    for (int s = 0; s < S_LEN; s++) {
        float z = zn;
        if (s + 1 < S_LEN) zn = g_zx[((s + 1) * B_SZ + b) * 32 + t];
        // h-matvec as two parallel 4-FMA chains
        float h0 = __shfl_sync(~0u, h, 0), h1 = __shfl_sync(~0u, h, 1);
        float h2 = __shfl_sync(~0u, h, 2), h3 = __shfl_sync(~0u, h, 3);
        float h4 = __shfl_sync(~0u, h, 4), h5 = __shfl_sync(~0u, h, 5);
        float h6 = __shfl_sync(~0u, h, 6), h7 = __shfl_sync(~0u, h, 7);
        float a0 = fmaf(h0, wh[0], fmaf(h1, wh[1], fmaf(h2, wh[2], h3 * wh[3])));
        float a1 = fmaf(h4, wh[4], fmaf(h5, wh[5], fmaf(h6, wh[6], h7 * wh[7])));
        z = z + a0 + a1;

        float p = __cosf(z);
        float cj[8];
        #pragma unroll
        for (int j = 0; j < 8; j++) cj[j] = __shfl_sync(~0u, p, (g << 3) + j);
        float acc = wo[7];
        #pragma unroll
        for (int j = 6; j >= 0; j--) acc = fmaf(cj[j + 1], acc, wo[j]);
        float pre = fmaf(cj[0], acc, bo);

        float act = (g == 2) ? fast_tanh(pre) : fast_sigmoid(pre);
        float af = __shfl_sync(~0u, act, q);
        float ii = __shfl_sync(~0u, act, 8 + q);
        float ag = __shfl_sync(~0u, act, 16 + q);
        float ao = __shfl_sync(~0u, act, 24 + q);
        c = fmaf(af, c, ii * ag);
        h = ao * fast_tanh(c);
        if (t < 8) g_h[(s * B_SZ + b) * H_DIM + t] = h;
    }
}

// ---------------------------------------------------------------------------
// Quantum head primitives. 256 amps/warp, idx = lane*8 + r; wire w <-> bit 7-w.
// All masks / register indices are COMPILE-TIME (template params).
// ---------------------------------------------------------------------------
template <int LM>
__device__ __forceinline__ void u2_lane_t(float (&ar)[8], float (&ai)[8],
                                          int lane, const float* __restrict__ u) {
    int myb = (lane & LM) ? 1 : 0;
    float dr = myb ? u[6] : u[0];
    float di = myb ? u[7] : u[1];
    float orr= myb ? u[4] : u[2];
    float oi = myb ? u[5] : u[3];
    #pragma unroll
    for (int r = 0; r < 8; r++) {
        float pr = __shfl_xor_sync(~0u, ar[r], LM);
        float pi = __shfl_xor_sync(~0u, ai[r], LM);
        float nr = dr * ar[r] - di * ai[r] + orr * pr - oi * pi;
        float ni = dr * ai[r] + di * ar[r] + orr * pi + oi * pr;
        ar[r] = nr; ai[r] = ni;
    }
}

template <int TM>
__device__ __forceinline__ void u2_reg_t(float (&ar)[8], float (&ai)[8],
                                         const float* __restrict__ u) {
    #pragma unroll
    for (int r = 0; r < 8; r++) {
        if ((r & TM) == 0) {
            const int r1 = r | TM;
            float a0r = ar[r], a0i = ai[r], a1r = ar[r1], a1i = ai[r1];
            ar[r]  = u[0]*a0r - u[1]*a0i + u[2]*a1r - u[3]*a1i;
            ai[r]  = u[0]*a0i + u[1]*a0r + u[2]*a1i + u[3]*a1r;
            ar[r1] = u[4]*a0r - u[5]*a0i + u[6]*a1r - u[7]*a1i;
            ai[r1] = u[4]*a0i + u[5]*a0r + u[6]*a1i + u[7]*a1r;
        }
    }
}

template <int P>
__device__ __forceinline__ void rz_t(float (&ar)[8], float (&ai)[8],
                                     int lane, float c, float s) {
    #pragma unroll
    for (int r = 0; r < 8; r++) {
        bool beta;
        if constexpr (P >= 3) beta = (lane >> (P - 3)) & 1;
        else                  beta = (r >> P) & 1;
        float sg = beta ? -s : s;
        float nr = fmaf(c, ar[r],  sg * ai[r]);
        float ni = fmaf(c, ai[r], -sg * ar[r]);
        ar[r] = nr; ai[r] = ni;
    }
}

template <int CM, int TM>
__device__ __forceinline__ void cnot_rr_tt(float (&ar)[8], float (&ai)[8]) {
    #pragma unroll
    for (int r = 0; r < 8; r++) {
        if (((r & CM) != 0) && ((r & TM) == 0)) {
            const int r1 = r | TM;
            float tr = ar[r]; ar[r] = ar[r1]; ar[r1] = tr;
            float ti = ai[r]; ai[r] = ai[r1]; ai[r1] = ti;
        }
    }
}

template <int TM>
__device__ __forceinline__ void cnot_lr_tt(float (&ar)[8], float (&ai)[8], int ctrl) {
    #pragma unroll
    for (int r = 0; r < 8; r++) {
        if ((r & TM) == 0) {
            const int r1 = r | TM;
            float tr = ctrl ? ar[r1] : ar[r];
            float t2 = ctrl ? ar[r]  : ar[r1];
            ar[r] = tr; ar[r1] = t2;
            float ti = ctrl ? ai[r1] : ai[r];
            float t3 = ctrl ? ai[r]  : ai[r1];
            ai[r] = ti; ai[r1] = t3;
        }
    }
}

template <int CM, int LT>
__device__ __forceinline__ void cnot_rl_tt(float (&ar)[8], float (&ai)[8]) {
    #pragma unroll
    for (int r = 0; r < 8; r++) {
        if ((r & CM) != 0) {     // r is an unrolled constant; ptxas folds this
            float sr = __shfl_xor_sync(~0u, ar[r], LT);
            float si = __shfl_xor_sync(~0u, ai[r], LT);
            ar[r] = sr; ai[r] = si;
        }
    }
}

template <int CM, int LT>
__device__ __forceinline__ void cnot_ll_tt(float (&ar)[8], float (&ai)[8], int lane) {
    int ctrl = (lane & CM) != 0;
    #pragma unroll
    for (int r = 0; r < 8; r++) {
        float sr = __shfl_xor_sync(~0u, ar[r], LT);
        float si = __shfl_xor_sync(~0u, ai[r], LT);
        if (ctrl) { ar[r] = sr; ai[r] = si; }
    }
}

template <int TM>
__device__ __forceinline__ void rx_reg(float (&ar)[8], float (&ai)[8], float c, float s) {
    #pragma unroll
    for (int r = 0; r < 8; r++) {
        if ((r & TM) == 0) {
            const int r1 = r | TM;
            float a0r = ar[r], a0i = ai[r], a1r = ar[r1], a1i = ai[r1];
            ar[r]  = fmaf(c, a0r,  s * a1i);  ai[r]  = fmaf(c, a0i, -s * a1r);
            ar[r1] = fmaf(c, a1r,  s * a0i);  ai[r1] = fmaf(c, a1i, -s * a0r);
        }
    }
}

template <int LM>
__device__ __forceinline__ void rx_lane(float (&ar)[8], float (&ai)[8], float c, float s) {
    #pragma unroll
    for (int r = 0; r < 8; r++) {
        float pr = __shfl_xor_sync(~0u, ar[r], LM);
        float pi = __shfl_xor_sync(~0u, ai[r], LM);
        float nr = fmaf(c, ar[r],  s * pi);
        float ni = fmaf(c, ai[r], -s * pr);
        ar[r] = nr; ai[r] = ni;
    }
}

// ---- fully unrolled random layer (structure from constexpr EM) ----
template <int O>
__device__ __forceinline__ void apply_all(float (&ar)[8], float (&ai)[8],
                                          int lane, const float* __restrict__ U) {
    if constexpr (O < EM.n) {
        constexpr int TY = EM.type[O];
        constexpr int A  = EM.a[O];
        constexpr int B  = EM.b[O];
        if constexpr (TY == 1) {                     // CNOT
            constexpr int PC = 7 - A, PT = 7 - B;
            if constexpr (PT < 3) {
                if constexpr (PC < 3) cnot_rr_tt<(1 << PC), (1 << PT)>(ar, ai);
                else cnot_lr_tt<(1 << PT)>(ar, ai, (lane >> (PC - 3)) & 1);
            } else {
                if constexpr (PC < 3) cnot_rl_tt<(1 << PC), (1 << (PT - 3))>(ar, ai);
                else cnot_ll_tt<(1 << (PC - 3)), (1 << (PT - 3))>(ar, ai, lane);
            }
        } else if constexpr (TY == 2) {              // fused RZ run
            rz_t<7 - A>(ar, ai, lane, U[O * 8 + 0], U[O * 8 + 1]);
        } else {                                     // general fused U2
            constexpr int P = 7 - A;
            if constexpr (P < 3) u2_reg_t<(1 << P)>(ar, ai, U + O * 8);
            else u2_lane_t<(1 << (P - 3))>(ar, ai, lane, U + O * 8);
        }
        apply_all<O + 1>(ar, ai, lane, U);
    }
}

// ---------------------------------------------------------------------------
// Kernel 3: quantum head + log-softmax. One warp per output row.
// ---------------------------------------------------------------------------
__global__ __launch_bounds__(128) void head_kernel(
    const float* __restrict__ phiq, const float* __restrict__ Whead,
    const float* __restrict__ b_head, float* __restrict__ out, QU P)
{
    int warp = (blockIdx.x * blockDim.x + threadIdx.x) >> 5;
    int lane = threadIdx.x & 31;
    int s_out = warp >> 7, b_out = warp & 127;
    const float* hsrc = g_h + ((b_out << 7) + s_out) * H_DIM;

    // RY(h) product-state init
    float myc = 1.f, mys = 0.f;
    if (lane < 8) __sincosf(hsrc[lane] * 0.5f, &mys, &myc);
    float lp = 1.f;
    #pragma unroll
    for (int w = 0; w < 5; w++) {
        float cw = __shfl_sync(~0u, myc, w);
        float sw = __shfl_sync(~0u, mys, w);
        lp *= ((lane >> (4 - w)) & 1) ? sw : cw;
    }
    float c5 = __shfl_sync(~0u, myc, 5), s5 = __shfl_sync(~0u, mys, 5);
    float c6 = __shfl_sync(~0u, myc, 6), s6 = __shfl_sync(~0u, mys, 6);
    float c7 = __shfl_sync(~0u, myc, 7), s7 = __shfl_sync(~0u, mys, 7);

    float ar[8], ai[8];
    #pragma unroll
    for (int r = 0; r < 8; r++) {
        ar[r] = lp * ((r & 4) ? s5 : c5) * ((r & 2) ? s6 : c6) * ((r & 1) ? s7 : c7);
        ai[r] = 0.f;
    }

    // fixed random layer, fully unrolled
    apply_all<0>(ar, ai, lane, P.u);

    // trainable RX(phiq)
    float pc = 1.f, ps = 0.f;
    if (lane < 8) __sincosf(phiq[lane] * 0.5f, &ps, &pc);
    {
        float cw, sw;
        cw = __shfl_sync(~0u, pc, 0); sw = __shfl_sync(~0u, ps, 0); rx_lane<16>(ar, ai, cw, sw);
        cw = __shfl_sync(~0u, pc, 1); sw = __shfl_sync(~0u, ps, 1); rx_lane<8>(ar, ai, cw, sw);
        cw = __shfl_sync(~0u, pc, 2); sw = __shfl_sync(~0u, ps, 2); rx_lane<4>(ar, ai, cw, sw);
        cw = __shfl_sync(~0u, pc, 3); sw = __shfl_sync(~0u, ps, 3); rx_lane<2>(ar, ai, cw, sw);
        cw = __shfl_sync(~0u, pc, 4); sw = __shfl_sync(~0u, ps, 4); rx_lane<1>(ar, ai, cw, sw);
        cw = __shfl_sync(~0u, pc, 5); sw = __shfl_sync(~0u, ps, 5); rx_reg<4>(ar, ai, cw, sw);
        cw = __shfl_sync(~0u, pc, 6); sw = __shfl_sync(~0u, ps, 6); rx_reg<2>(ar, ai, cw, sw);
        cw = __shfl_sync(~0u, pc, 7); sw = __shfl_sync(~0u, ps, 7); rx_reg<1>(ar, ai, cw, sw);
    }

    // measure <Z_w>
    float p[8], tot = 0.f;
    #pragma unroll
    for (int r = 0; r < 8; r++) {
        p[r] = ar[r] * ar[r] + ai[r] * ai[r];
        tot += p[r];
    }
    float z[8];
    #pragma unroll
    for (int w = 0; w < 5; w++) z[w] = ((lane >> (4 - w)) & 1) ? -tot : tot;
    z[5] = (p[0] + p[1] + p[2] + p[3]) - (p[4] + p[5] + p[6] + p[7]);
    z[6] = (p[0] + p[1] + p[4] + p[5]) - (p[2] + p[3] + p[6] + p[7]);
    z[7] = (p[0] + p[2] + p[4] + p[6]) - (p[1] + p[3] + p[5] + p[7]);
    #pragma unroll
    for (int w = 0; w < 8; w++) {
        #pragma unroll
        for (int off = 16; off; off >>= 1)
            z[w] += __shfl_xor_sync(~0u, z[w], off);
    }

    // logits + log-softmax over 12 classes
    float logit = -1e30f;
    if (lane < 12) {
        logit = b_head[lane];
        #pragma unroll
        for (int k = 0; k < 8; k++) logit = fmaf(z[k], Whead[lane * 8 + k], logit);
    }
    float mx = logit;
    #pragma unroll
    for (int off = 8; off; off >>= 1) mx = fmaxf(mx, __shfl_xor_sync(~0u, mx, off, 16));
    float e = (lane < 12) ? __expf(logit - mx) : 0.f;
    float se = e;
    #pragma unroll
    for (int off = 8; off; off >>= 1) se += __shfl_xor_sync(~0u, se, off, 16);
    if (lane < 12) out[warp * T_OUT + lane] = logit - mx - __logf(se);
}

// ---------------------------------------------------------------------------
// Host: numpy-legacy MT19937 (RandomState(1234)) + gate fusion -> coefficients.
// Emission order mirrors constexpr compute_emitted() exactly.
// ---------------------------------------------------------------------------
namespace {
struct MTState { uint32_t mt[624]; int mti; };

static void mt_seed(MTState& s, uint32_t seed) {
    s.mt[0] = seed;
    for (int i = 1; i < 624; i++)
        s.mt[i] = 1812433253u * (s.mt[i - 1] ^ (s.mt[i - 1] >> 30)) + (uint32_t)i;
    s.mti = 624;
}
static uint32_t mt_next(MTState& s) {
    if (s.mti >= 624) {
        for (int i = 0; i < 624; i++) {
            uint32_t y = (s.mt[i] & 0x80000000u) | (s.mt[(i + 1) % 624] & 0x7fffffffu);
            s.mt[i] = s.mt[(i + 397) % 624] ^ (y >> 1) ^ ((y & 1u) ? 0x9908b0dfu : 0u);
        }
        s.mti = 0;
    }
    uint32_t y = s.mt[s.mti++];
    y ^= y >> 11;
    y ^= (y << 7) & 0x9d2c5680u;
    y ^= (y << 15) & 0xefc60000u;
    y ^= y >> 18;
    return y;
}
static uint32_t np_randint(MTState& s, uint32_t n) {
    uint32_t rng = n - 1;
    uint32_t mask = rng;
    mask |= mask >> 1; mask |= mask >> 2; mask |= mask >> 4;
    mask |= mask >> 8; mask |= mask >> 16;
    uint32_t v;
    do { v = mt_next(s) & mask; } while (v > rng);
    return v;
}
static double np_double(MTState& s) {
    uint32_t a = mt_next(s) >> 5;
    uint32_t b = mt_next(s) >> 6;
    return ((double)a * 67108864.0 + (double)b) / 9007199254740992.0;
}

typedef std::complex<double> cd;

struct Pend {
    cd m[2][2];
    int count;
    bool allrz;
    void reset() { m[0][0] = 1.0; m[0][1] = 0.0; m[1][0] = 0.0; m[1][1] = 1.0; count = 0; allrz = true; }
};

static void build_u(QU& P) {
    MTState m;
    mt_seed(m, 1234u);

    Pend pend[8];
    for (int w = 0; w < 8; w++) pend[w].reset();
    int n = 0;

    auto flush = [&](int w) {
        if (!pend[w].count) return;
        float* u = &P.u[n * 8];
        if (pend[w].allrz) {
            u[0] = (float)pend[w].m[0][0].real();
            u[1] = (float)(-pend[w].m[0][0].imag());
        } else {
            u[0] = (float)pend[w].m[0][0].real(); u[1] = (float)pend[w].m[0][0].imag();
            u[2] = (float)pend[w].m[0][1].real(); u[3] = (float)pend[w].m[0][1].imag();
            u[4] = (float)pend[w].m[1][0].real(); u[5] = (float)pend[w].m[1][0].imag();
            u[6] = (float)pend[w].m[1][1].real(); u[7] = (float)pend[w].m[1][1].imag();
        }
        n++;
        pend[w].reset();
    };

    for (int k = 0; k < N_RAW; k++) {
        uint32_t kind = np_randint(m, 4);
        if (kind == 3) {
            int c = (int)np_randint(m, 8);
            int t = (int)np_randint(m, 7);
            if (t >= c) t++;
            flush(c); flush(t);
            n++;                       // CNOT slot (no coefficients)
        } else {
            int g = (int)(kind % 3);
            int w = (int)np_randint(m, 8);
            double ang = 6.283185307179586 * np_double(m);
            double th = (double)(float)ang;
            double c = cos(th * 0.5), s = sin(th * 0.5);
            cd R[2][2];
            if (g == 0) {
                R[0][0] = c; R[0][1] = cd(0, -s);
                R[1][0] = cd(0, -s); R[1][1] = c;
            } else if (g == 1) {
                R[0][0] = c; R[0][1] = -s;
                R[1][0] = s; R[1][1] = c;
            } else {
                R[0][0] = cd(c, -s); R[0][1] = 0.0;
                R[1][0] = 0.0; R[1][1] = cd(c, s);
            }
            cd n00 = R[0][0] * pend[w].m[0][0] + R[0][1] * pend[w].m[1][0];
            cd n01 = R[0][0] * pend[w].m[0][1] + R[0][1] * pend[w].m[1][1];
            cd n10 = R[1][0] * pend[w].m[0][0] + R[1][1] * pend[w].m[1][0];
            cd n11 = R[1][0] * pend[w].m[0][1] + R[1][1] * pend[w].m[1][1];
            pend[w].m[0][0] = n00; pend[w].m[0][1] = n01;
            pend[w].m[1][0] = n10; pend[w].m[1][1] = n11;
            pend[w].count++;
            if (g != 2) pend[w].allrz = false;
        }
    }
    for (int w = 0; w < 8; w++) flush(w);
}
} // namespace

// ---------------------------------------------------------------------------
extern "C" void kernel_launch(void* const* d_in, const int* in_sizes, int n_in,
                              void* d_out, int out_size) {
    (void)in_sizes; (void)n_in; (void)out_size;
    const float* emb    = (const float*)d_in[0];
    const float* Win    = (const float*)d_in[1];
    const float* b_in   = (const float*)d_in[2];
    const float* phi    = (const float*)d_in[3];
    const float* Wout   = (const float*)d_in[4];
    const float* b_out  = (const float*)d_in[5];
    const float* phiq   = (const float*)d_in[6];
    const float* Whead  = (const float*)d_in[7];
    const float* b_head = (const float*)d_in[8];
    const int*   sent   = (const int*)d_in[9];

    QU P{};
    build_u(P);

    zx_kernel<<<NROWS / 4, 128>>>(emb, Win, b_in, phi, sent);
    scan_kernel<<<B_SZ, 32>>>(Win, Wout, b_out);
    head_kernel<<<NROWS / 4, 128>>>(phiq, Whead, b_head, (float*)d_out, P);
}